// round 17
// baseline (speedup 1.0000x reference)
#include <cuda_runtime.h>

#define BB 256
#define TT 512
#define DD 50
#define HH 128
#define G4 512
#define HID 256

typedef unsigned long long ull;

// ---- device scratch ----
__device__ float g_xgT[2][TT][G4][BB];   // input-gate preactivations [d][t][row][b]

__device__ __forceinline__ float sigf(float x)   { return 1.0f / (1.0f + __expf(-x)); }
__device__ __forceinline__ float tanhf_(float x) { return 2.0f / (1.0f + __expf(-2.0f * x)) - 1.0f; }

__device__ __forceinline__ ull pack2(float a, float b) {
    ull r; asm("mov.b64 %0,{%1,%2};" : "=l"(r) : "f"(a), "f"(b)); return r;
}
__device__ __forceinline__ void unpack2(ull v, float& a, float& b) {
    asm("mov.b64 {%0,%1},%2;" : "=f"(a), "=f"(b) : "l"(v));
}
__device__ __forceinline__ void fma2(ull a, ull b, ull& c) {
    asm("fma.rn.f32x2 %0,%1,%2,%0;" : "+l"(c) : "l"(a), "l"(b));
}
__device__ __forceinline__ ull add2(ull a, ull b) {
    ull r; asm("add.rn.f32x2 %0,%1,%2;" : "=l"(r) : "l"(a), "l"(b)); return r;
}
__device__ __forceinline__ unsigned smem_u32(const void* p) {
    unsigned r;
    asm("{ .reg .u64 t; cvta.to.shared.u64 t, %1; cvt.u32.u64 %0, t; }" : "=r"(r) : "l"(p));
    return r;
}
__device__ __forceinline__ void mbar_wait(unsigned mb, int phase) {
    asm volatile(
        "{\n\t.reg .pred P;\n"
        "W%=:\n\t"
        "mbarrier.try_wait.parity.acquire.cluster.shared::cta.b64 P, [%0], %1, 0x989680;\n\t"
        "@!P bra W%=;\n\t}"
        :: "r"(mb), "r"(phase) : "memory");
}

// ---------------------------------------------------------------------------
// Embedding lookup + input-gate GEMM -> transposed xg (unchanged)
// ---------------------------------------------------------------------------
__global__ void __launch_bounds__(256) embed_gemm(
    const int*   __restrict__ idx,
    const float* __restrict__ emb,
    const float* __restrict__ Wih_f, const float* __restrict__ bih_f, const float* __restrict__ bhh_f,
    const float* __restrict__ Wih_b, const float* __restrict__ bih_b, const float* __restrict__ bhh_b)
{
    __shared__ __align__(16) float xsA[16 * DD * 2];
    const int tid = threadIdx.x;
    const int b0  = blockIdx.x * 32;
    const int t   = blockIdx.y;

    for (int i = tid; i < 32 * DD; i += 256) {
        int b = i / DD, k = i - b * DD;
        int id = idx[(b0 + b) * TT + t];
        xsA[(b >> 1) * (2 * DD) + k * 2 + (b & 1)] = emb[id * DD + k];
    }
    __syncthreads();

    #pragma unroll 1
    for (int g = 0; g < 4; ++g) {
        int col = tid + g * 256;
        int dir = col >> 9;
        int n   = col & 511;
        const float* W = dir ? Wih_b : Wih_f;
        float bias = dir ? (bih_b[n] + bhh_b[n]) : (bih_f[n] + bhh_f[n]);

        float w[DD];
        #pragma unroll
        for (int k = 0; k < DD; ++k) w[k] = W[n * DD + k];

        ull acc[16];
        ull bp2 = pack2(bias, bias);
        #pragma unroll
        for (int p = 0; p < 16; ++p) acc[p] = bp2;

        #pragma unroll 2
        for (int k = 0; k < DD; ++k) {
            ull w2 = pack2(w[k], w[k]);
            #pragma unroll
            for (int p = 0; p < 16; ++p) {
                ull x = *(const ull*)&xsA[p * (2 * DD) + k * 2];
                fma2(x, w2, acc[p]);
            }
        }

        float* dst = &g_xgT[dir][t][n][b0];
        #pragma unroll
        for (int p = 0; p < 16; ++p) {
            float a, b; unpack2(acc[p], a, b);
            *(float2*)&dst[2 * p] = make_float2(a, b);
        }
    }
}

// ---------------------------------------------------------------------------
// Persistent LSTM recurrence — R12 design with the aligned cluster barrier
// replaced by an mbarrier full-handshake:
//   full[parity] mbarrier per CTA, arrive-count 32 (8 warps x 4 CTAs).
//   After pushes: __syncwarp, lane0 -> 4x mbarrier.arrive.release.cluster.
//   Before MAC:  try_wait.parity.acquire.cluster (~100 cyc vs ~490 aligned).
// Write-after-read is transitively ordered through the full barrier (double
// buffer + parity), so no empty barrier is needed.
// ---------------------------------------------------------------------------
#define SEC_W  132                 // words per 16-k section (16*8 + 4 pad)
#define HB_W   (8 * SEC_W)         // 1056 words per buffer

__global__ void __launch_bounds__(256, 2) __cluster_dims__(4, 1, 1)
lstm_mb(const float* __restrict__ Whh_f, const float* __restrict__ Whh_b,
        const float* __restrict__ masks, float* __restrict__ out)
{
    __shared__ __align__(16) float hb[2][HB_W];
    __shared__ __align__(8)  ull   mbfull[2];

    const int tid  = threadIdx.x;
    const int kq   = blockIdx.x;             // k-quarter == cluster rank
    const int bt   = blockIdx.y;
    const int d    = blockIdx.z;
    const int K0   = kq * 32;
    const int bb0  = bt * 8;
    const int lane = tid & 31;
    const int warp = tid >> 5;

    const int kkl   = lane & 3;
    const int kgrp  = lane >> 2;             // 0..7 (lane bits 2..4 -> xor 4,8,16)
    const int kk    = warp * 4 + kkl;        // 0..31
    const int kglob = K0 + kk;
    const int bu    = bb0 + kgrp;            // owned batch

    const float* Whh = d ? Whh_b : Whh_f;

    // ---- weights: 4 gate rows x own 16-k slice, in registers ----
    float w[4][16];
    #pragma unroll
    for (int g = 0; g < 4; ++g) {
        const float4* src = (const float4*)&Whh[(g * 128 + kglob) * 128 + kgrp * 16];
        #pragma unroll
        for (int q = 0; q < 4; ++q) {
            float4 v = src[q];
            w[g][4 * q + 0] = v.x; w[g][4 * q + 1] = v.y;
            w[g][4 * q + 2] = v.z; w[g][4 * q + 3] = v.w;
        }
    }

    // zero h buffer 0; init mbarriers
    for (int i = tid; i < HB_W; i += 256) hb[0][i] = 0.f;
    if (tid == 0) {
        asm volatile("mbarrier.init.shared.b64 [%0], %1;"
                     :: "r"(smem_u32(&mbfull[0])), "r"(32u) : "memory");
        asm volatile("mbarrier.init.shared.b64 [%0], %1;"
                     :: "r"(smem_u32(&mbfull[1])), "r"(32u) : "memory");
    }
    __syncthreads();
    // cluster-wide: all CTAs' mbarriers initialized before any peer arrives
    asm volatile("barrier.cluster.arrive.aligned;" ::: "memory");
    asm volatile("barrier.cluster.wait.aligned;"   ::: "memory");

    // ---- h store word (q-permuted, as in R12) + peer push addresses ----
    const int hs  = kglob >> 4;
    const int hq  = ((kgrp >> 1) ^ (hs >> 1)) & 3;
    const int hw  = hs * SEC_W + (kglob & 15) * 8 + hq * 2 + (kgrp & 1);
    float* loc0 = &hb[0][hw];
    const unsigned par_off = (unsigned)(HB_W * 4);   // hb[1] - hb[0] bytes
    unsigned rem0[3];
    {
        unsigned a0 = smem_u32(&hb[0][0]) + (unsigned)(hw * 4);
        #pragma unroll
        for (int p = 0; p < 3; ++p) {
            unsigned pr = (kq + 1 + p) & 3;
            asm("mapa.shared::cluster.u32 %0, %1, %2;" : "=r"(rem0[p]) : "r"(a0), "r"(pr));
        }
    }
    // mbarrier addresses (own + 3 peers) for both parities, cluster-mapped
    unsigned mbr[2][4];
    #pragma unroll
    for (int p2 = 0; p2 < 2; ++p2) {
        unsigned a = smem_u32(&mbfull[p2]);
        #pragma unroll
        for (int p = 0; p < 4; ++p) {
            unsigned pr = (kq + p) & 3;   // includes self (p=0)
            asm("mapa.shared::cluster.u32 %0, %1, %2;" : "=r"(mbr[p2][p]) : "r"(a), "r"(pr));
        }
    }
    const unsigned mb_loc[2] = { smem_u32(&mbfull[0]), smem_u32(&mbfull[1]) };

    // ---- per-thread state ----
    float c = 0.f, m = -3.0e38f;

    const int tstep = d ? -1 : 1;
    int t = d ? (TT - 1) : 0;

    // prefetch xg (4 gate rows, own batch) + mask penalty for step 0
    float xn0, xn1, xn2, xn3, pen;
    {
        const float* p = &g_xgT[d][t][0][bu];
        xn0 = __ldg(p + (0 * 128 + kglob) * BB);
        xn1 = __ldg(p + (1 * 128 + kglob) * BB);
        xn2 = __ldg(p + (2 * 128 + kglob) * BB);
        xn3 = __ldg(p + (3 * 128 + kglob) * BB);
        pen = (1.0f - __ldg(&masks[bu * TT + t])) * 1e8f;
    }

    int cur = 0;
    for (int s = 0; s < TT; ++s) {
        float cx0 = xn0, cx1 = xn1, cx2 = xn2, cx3 = xn3, cpen = pen;
        // prefetch next step (issues before the wait below)
        {
            int t2 = t + tstep;
            t2 = (t2 < 0) ? 0 : (t2 > TT - 1 ? TT - 1 : t2);
            const float* p = &g_xgT[d][t2][0][bu];
            xn0 = __ldg(p + (0 * 128 + kglob) * BB);
            xn1 = __ldg(p + (1 * 128 + kglob) * BB);
            xn2 = __ldg(p + (2 * 128 + kglob) * BB);
            xn3 = __ldg(p + (3 * 128 + kglob) * BB);
            pen = (1.0f - __ldg(&masks[bu * TT + t2])) * 1e8f;
        }

        // wait for all peers' step-(s-1) h pushes into hb[cur]
        if (s > 0) {
            int ph = ((s - 1) >> 1) & 1;
            mbar_wait(mb_loc[cur], ph);
        }

        // ---- MAC: own 16-k slice, 4 gates x 4 q-slots (q-permuted pairs) ----
        ull A[4][4];
        #pragma unroll
        for (int g = 0; g < 4; ++g)
            #pragma unroll
            for (int q = 0; q < 4; ++q) A[g][q] = 0ull;

        const float* hc = &hb[cur][kgrp * SEC_W];
        #pragma unroll
        for (int i = 0; i < 16; ++i) {
            ulonglong2 hA = *(const ulonglong2*)(hc + i * 8);      // q=0, q=1
            ulonglong2 hB = *(const ulonglong2*)(hc + i * 8 + 4);  // q=2, q=3
            #pragma unroll
            for (int g = 0; g < 4; ++g) {
                ull w2 = pack2(w[g][i], w[g][i]);
                fma2(hA.x, w2, A[g][0]);
                fma2(hA.y, w2, A[g][1]);
                fma2(hB.x, w2, A[g][2]);
                fma2(hB.y, w2, A[g][3]);
            }
        }

        // ---- narrowing butterfly over 8 kgrps (32 SHFL + 16 add2) ----
        #pragma unroll
        for (int g = 0; g < 4; ++g) {
            A[g][0] = add2(A[g][0], __shfl_xor_sync(0xffffffffu, A[g][2], 16));
            A[g][1] = add2(A[g][1], __shfl_xor_sync(0xffffffffu, A[g][3], 16));
        }
        #pragma unroll
        for (int g = 0; g < 4; ++g)
            A[g][0] = add2(A[g][0], __shfl_xor_sync(0xffffffffu, A[g][1], 8));
        #pragma unroll
        for (int g = 0; g < 4; ++g)
            A[g][0] = add2(A[g][0], __shfl_xor_sync(0xffffffffu, A[g][0], 4));

        // ---- update: lane owns (kglob, bu); pick hie half of A[g][0] ----
        const int hie = kgrp & 1;
        float aa, bb2, gi, gf, gg, go;
        unpack2(A[0][0], aa, bb2); gi = hie ? bb2 : aa;
        unpack2(A[1][0], aa, bb2); gf = hie ? bb2 : aa;
        unpack2(A[2][0], aa, bb2); gg = hie ? bb2 : aa;
        unpack2(A[3][0], aa, bb2); go = hie ? bb2 : aa;
        gi += cx0; gf += cx1; gg += cx2; go += cx3;

        c = sigf(gf) * c + sigf(gi) * tanhf_(gg);
        float hv = sigf(go) * tanhf_(c);
        m = fmaxf(m, hv - cpen);

        if (s < TT - 1) {
            // write next h buffer: local + 3 DSMEM peers (4B each)
            unsigned nb = cur ? 0u : par_off;
            *(float*)((char*)loc0 + nb) = hv;
            asm volatile("st.shared::cluster.f32 [%0], %1;" :: "r"(rem0[0] + nb), "f"(hv) : "memory");
            asm volatile("st.shared::cluster.f32 [%0], %1;" :: "r"(rem0[1] + nb), "f"(hv) : "memory");
            asm volatile("st.shared::cluster.f32 [%0], %1;" :: "r"(rem0[2] + nb), "f"(hv) : "memory");
            // warp-aggregated release: syncwarp orders the warp's stores,
            // lane0 arrives on all 4 CTAs' full[next-parity] barriers
            __syncwarp();
            if (lane == 0) {
                const int nxt = cur ^ 1;
                asm volatile("mbarrier.arrive.release.cluster.shared::cluster.b64 _, [%0];"
                             :: "r"(mbr[nxt][0]) : "memory");
                asm volatile("mbarrier.arrive.release.cluster.shared::cluster.b64 _, [%0];"
                             :: "r"(mbr[nxt][1]) : "memory");
                asm volatile("mbarrier.arrive.release.cluster.shared::cluster.b64 _, [%0];"
                             :: "r"(mbr[nxt][2]) : "memory");
                asm volatile("mbarrier.arrive.release.cluster.shared::cluster.b64 _, [%0];"
                             :: "r"(mbr[nxt][3]) : "memory");
            }
        }

        cur ^= 1;
        t += tstep;
    }

    out[bu * HID + d * HH + kglob] = m;
}

// ---------------------------------------------------------------------------
extern "C" void kernel_launch(void* const* d_in, const int* in_sizes, int n_in,
                              void* d_out, int out_size)
{
    (void)in_sizes; (void)n_in; (void)out_size;
    const int*   idx   = (const int*)  d_in[0];
    const float* masks = (const float*)d_in[1];
    const float* emb   = (const float*)d_in[2];
    const float* Wih_f = (const float*)d_in[3];
    const float* Whh_f = (const float*)d_in[4];
    const float* bih_f = (const float*)d_in[5];
    const float* bhh_f = (const float*)d_in[6];
    const float* Wih_b = (const float*)d_in[7];
    const float* Whh_b = (const float*)d_in[8];
    const float* bih_b = (const float*)d_in[9];
    const float* bhh_b = (const float*)d_in[10];
    float* out = (float*)d_out;

    embed_gemm<<<dim3(8, TT), 256>>>(idx, emb, Wih_f, bih_f, bhh_f,
                                     Wih_b, bih_b, bhh_b);
    lstm_mb<<<dim3(4, 32, 2), 256>>>(Whh_f, Whh_b, masks, out);
}